// round 1
// baseline (speedup 1.0000x reference)
#include <cuda_runtime.h>
#include <math.h>

#define S_LEN 2048
#define HID 2048
#define NK 16
#define NV 32
#define DK 128
#define DV 128
#define KSZ 4
#define CHUNK 64
#define NCHUNK (S_LEN / CHUNK)
#define KEY_DIM (NK * DK)          // 2048
#define VAL_DIM (NV * DV)          // 4096
#define CONV_DIM (2 * KEY_DIM + VAL_DIM)  // 8192

// ---------------- scratch (static device globals; no allocation) ----------------
__device__ float d_mixed[(size_t)S_LEN * CONV_DIM];   // pre-conv projections
__device__ float d_conv[(size_t)S_LEN * CONV_DIM];    // post conv + silu
__device__ float d_zbuf[(size_t)S_LEN * VAL_DIM];
__device__ float d_g[NV * S_LEN];                     // per-chunk cumsum'd gate, [h][s]
__device__ float d_beta[NV * S_LEN];                  // [h][s]
__device__ float d_qn[(size_t)S_LEN * NK * DK];       // l2norm(q) * DK^-0.5
__device__ float d_kn[(size_t)S_LEN * NK * DK];       // l2norm(k)
__device__ float d_u[(size_t)NV * S_LEN * DV];        // [h][s][dv]
__device__ float d_kcd[(size_t)NV * S_LEN * DK];      // [h][s][dk]
__device__ float d_scores[(size_t)NV * NCHUNK * CHUNK * CHUNK];
__device__ float d_o[(size_t)S_LEN * VAL_DIM];        // core output, [s][h*DV+dv]
__device__ float d_hbuf[(size_t)S_LEN * VAL_DIM];     // gated+normed

// ---------------- generic SGEMM: C[M,N] = A[M,K] @ B[N,K]^T ----------------
// 128x128 tile, BK=16, 256 threads, 8x8 per thread. M,N multiples of 128; K of 16.
__global__ __launch_bounds__(256) void sgemm_tn(
    const float* __restrict__ A, const float* __restrict__ B,
    float* __restrict__ C, int M, int N, int K) {
    __shared__ float As[16][128];
    __shared__ float Bs[16][128];
    int tid = threadIdx.x;
    int bm = blockIdx.y * 128, bn = blockIdx.x * 128;
    int ty = tid >> 4, tx = tid & 15;
    float acc[8][8];
#pragma unroll
    for (int i = 0; i < 8; i++)
#pragma unroll
        for (int j = 0; j < 8; j++) acc[i][j] = 0.f;

    for (int k0 = 0; k0 < K; k0 += 16) {
#pragma unroll
        for (int l = 0; l < 2; l++) {
            int id = tid + l * 256;           // 0..511
            int row = id >> 2;                // 0..127
            int c4 = (id & 3) << 2;           // 0,4,8,12
            float4 av = *(const float4*)(A + (size_t)(bm + row) * K + k0 + c4);
            As[c4 + 0][row] = av.x; As[c4 + 1][row] = av.y;
            As[c4 + 2][row] = av.z; As[c4 + 3][row] = av.w;
            float4 bv = *(const float4*)(B + (size_t)(bn + row) * K + k0 + c4);
            Bs[c4 + 0][row] = bv.x; Bs[c4 + 1][row] = bv.y;
            Bs[c4 + 2][row] = bv.z; Bs[c4 + 3][row] = bv.w;
        }
        __syncthreads();
#pragma unroll
        for (int kk = 0; kk < 16; kk++) {
            float a[8], b[8];
#pragma unroll
            for (int i = 0; i < 8; i++) a[i] = As[kk][ty * 8 + i];
#pragma unroll
            for (int j = 0; j < 8; j++) b[j] = Bs[kk][tx * 8 + j];
#pragma unroll
            for (int i = 0; i < 8; i++)
#pragma unroll
                for (int j = 0; j < 8; j++) acc[i][j] += a[i] * b[j];
        }
        __syncthreads();
    }
#pragma unroll
    for (int i = 0; i < 8; i++) {
        float* cp = C + (size_t)(bm + ty * 8 + i) * N + bn + tx * 8;
        float4 v0 = make_float4(acc[i][0], acc[i][1], acc[i][2], acc[i][3]);
        float4 v1 = make_float4(acc[i][4], acc[i][5], acc[i][6], acc[i][7]);
        *(float4*)cp = v0;
        *(float4*)(cp + 4) = v1;
    }
}

// ---------------- a/b projections -> raw g and beta ----------------
// one warp per (s, head, which). which=0 -> g (from a), which=1 -> beta (from b)
__global__ __launch_bounds__(256) void proj_ab(
    const float* __restrict__ x, const float* __restrict__ Wa,
    const float* __restrict__ Wb, const float* __restrict__ dt_bias,
    const float* __restrict__ A_log) {
    int gw = (blockIdx.x * 256 + threadIdx.x) >> 5;
    int lane = threadIdx.x & 31;
    int which = gw & 1;
    int h = (gw >> 1) & (NV - 1);
    int s = gw >> 6;
    const float* xr = x + (size_t)s * HID;
    const float* wr = (which ? Wb : Wa) + (size_t)h * HID;
    float sum = 0.f;
    for (int i = lane * 4; i < HID; i += 128) {
        float4 a = *(const float4*)(xr + i);
        float4 b = *(const float4*)(wr + i);
        sum += a.x * b.x + a.y * b.y + a.z * b.z + a.w * b.w;
    }
#pragma unroll
    for (int o = 16; o; o >>= 1) sum += __shfl_xor_sync(0xffffffffu, sum, o);
    if (lane == 0) {
        if (which) {
            d_beta[h * S_LEN + s] = 1.f / (1.f + expf(-sum));
        } else {
            float xv = sum + dt_bias[h];
            float sp = fmaxf(xv, 0.f) + log1pf(expf(-fabsf(xv)));  // stable softplus
            d_g[h * S_LEN + s] = -expf(A_log[h]) * sp;
        }
    }
}

// ---------------- per-chunk inclusive cumsum of g ----------------
__global__ void g_cumsum() {
    int h = blockIdx.x >> 5;       // NCHUNK = 32
    int c = blockIdx.x & 31;
    __shared__ float buf[CHUNK];
    int i = threadIdx.x;
    buf[i] = d_g[h * S_LEN + c * CHUNK + i];
    __syncthreads();
#pragma unroll
    for (int off = 1; off < CHUNK; off <<= 1) {
        float v = (i >= off) ? buf[i - off] : 0.f;
        __syncthreads();
        buf[i] += v;
        __syncthreads();
    }
    d_g[h * S_LEN + c * CHUNK + i] = buf[i];
}

// ---------------- causal depthwise conv (K=4) + SiLU ----------------
__global__ __launch_bounds__(256) void conv_silu(const float* __restrict__ w) {
    int idx = blockIdx.x * 256 + threadIdx.x;  // S*CONV_DIM = 16.7M
    int c = idx % CONV_DIM;
    int s = idx / CONV_DIM;
    float acc = 0.f;
#pragma unroll
    for (int t = 0; t < KSZ; t++) {
        int sp = s - (KSZ - 1) + t;
        if (sp >= 0) acc += d_mixed[(size_t)sp * CONV_DIM + c] * w[c * KSZ + t];
    }
    d_conv[idx] = acc / (1.f + expf(-acc));  // silu
}

// ---------------- l2norm of q,k (16 source heads); q also * DK^-0.5 ----------------
__global__ __launch_bounds__(256) void qk_norm() {
    int gw = (blockIdx.x * 256 + threadIdx.x) >> 5;  // S*NK*2 warps
    int lane = threadIdx.x & 31;
    int which = gw & 1;                 // 0=q, 1=k
    int hk = (gw >> 1) & (NK - 1);
    int s = gw >> 5;
    const float* src = d_conv + (size_t)s * CONV_DIM + which * KEY_DIM + hk * DK + lane * 4;
    float4 v = *(const float4*)src;
    float ss = v.x * v.x + v.y * v.y + v.z * v.z + v.w * v.w;
#pragma unroll
    for (int o = 16; o; o >>= 1) ss += __shfl_xor_sync(0xffffffffu, ss, o);
    float r = rsqrtf(ss + 1e-6f);
    if (!which) r *= 0.08838834764831845f;  // DK^-0.5
    float* dst = (which ? d_kn : d_qn) + ((size_t)s * NK + hk) * DK + lane * 4;
    v.x *= r; v.y *= r; v.z *= r; v.w *= r;
    *(float4*)dst = v;
}

// ---------------- chunk-local: scores, UT transform, u, kcd ----------------
// one block per (chunk, head). 256 threads.
#define PADK 132
__global__ __launch_bounds__(256) void chunk_kernel() {
    int cid = blockIdx.x;
    int h = blockIdx.y;
    int h2 = h >> 1;                 // q/k source head (repeat ratio 2)
    int s0 = cid * CHUNK;
    extern __shared__ float sm[];
    float* Ks = sm;                    // 64*132 (normalized k)
    float* KBs = Ks + 64 * PADK;       // 64*132 (k*beta, later v*beta)
    float* Qs = KBs + 64 * PADK;       // 64*132
    float* Am = Qs + 64 * PADK;        // 64*64
    float* gc = Am + 64 * 64;          // 64
    float* bt = gc + 64;               // 64
    float* rowbuf = bt + 64;           // 64
    int tid = threadIdx.x;

    if (tid < 64) {
        gc[tid] = d_g[h * S_LEN + s0 + tid];
        bt[tid] = d_beta[h * S_LEN + s0 + tid];
    }
    __syncthreads();

    // load k, q, kb
    for (int t = tid; t < 64 * 32; t += 256) {
        int r = t >> 5, c4 = (t & 31) << 2;
        float4 kv = *(const float4*)&d_kn[((size_t)(s0 + r) * NK + h2) * DK + c4];
        float4 qv = *(const float4*)&d_qn[((size_t)(s0 + r) * NK + h2) * DK + c4];
        float b = bt[r];
        Ks[r * PADK + c4 + 0] = kv.x; Ks[r * PADK + c4 + 1] = kv.y;
        Ks[r * PADK + c4 + 2] = kv.z; Ks[r * PADK + c4 + 3] = kv.w;
        Qs[r * PADK + c4 + 0] = qv.x; Qs[r * PADK + c4 + 1] = qv.y;
        Qs[r * PADK + c4 + 2] = qv.z; Qs[r * PADK + c4 + 3] = qv.w;
        KBs[r * PADK + c4 + 0] = kv.x * b; KBs[r * PADK + c4 + 1] = kv.y * b;
        KBs[r * PADK + c4 + 2] = kv.z * b; KBs[r * PADK + c4 + 3] = kv.w * b;
    }
    __syncthreads();

    // scores[i][j] = (q_i . k_j) * exp(gc_i - gc_j), i>=j   (stored to gmem)
    // Am[i][j]     = -(kb_i . k_j) * exp(gc_i - gc_j), i>j
    for (int t = tid; t < 4096; t += 256) {
        int i = t >> 6, j = t & 63;
        float sc = 0.f, am = 0.f;
        if (i >= j) {
            float dq = 0.f, dk = 0.f;
            const float* kr = Ks + j * PADK;
            const float* qr = Qs + i * PADK;
            const float* kbr = KBs + i * PADK;
#pragma unroll 4
            for (int d = 0; d < 128; d++) {
                float kj = kr[d];
                dq += qr[d] * kj;
                dk += kbr[d] * kj;
            }
            float e = expf(gc[i] - gc[j]);
            sc = dq * e;
            if (i > j) am = -dk * e;
        }
        d_scores[(size_t)(h * NCHUNK + cid) * 4096 + t] = sc;
        Am[t] = am;
    }
    __syncthreads();

    // UT transform (forward substitution), sequential over rows
    for (int i = 1; i < 64; i++) {
        if (tid < i) {
            int j = tid;
            float sum = Am[i * 64 + j];
            for (int k = j + 1; k < i; k++) sum += Am[i * 64 + k] * Am[k * 64 + j];
            rowbuf[j] = sum;
        }
        __syncthreads();
        if (tid < i) Am[i * 64 + tid] = rowbuf[tid];
        __syncthreads();
    }

    // scale kb rows by exp(gc) in place (for kcd)
    if (tid < 64) rowbuf[tid] = expf(gc[tid]);
    __syncthreads();
    for (int t = tid; t < 64 * 128; t += 256) {
        int r = t >> 7, d = t & 127;
        KBs[r * PADK + d] *= rowbuf[r];
    }
    __syncthreads();

    // kcd = (Am + I) @ (kb*exp(gc))
    for (int t = tid; t < 8192; t += 256) {
        int i = t >> 7, dk = t & 127;
        float acc = KBs[i * PADK + dk];
        for (int j = 0; j < i; j++) acc += Am[i * 64 + j] * KBs[j * PADK + dk];
        d_kcd[((size_t)h * S_LEN + s0 + i) * DK + dk] = acc;
    }
    __syncthreads();

    // overwrite KBs with v*beta
    for (int t = tid; t < 64 * 32; t += 256) {
        int r = t >> 5, c4 = (t & 31) << 2;
        float4 vv = *(const float4*)&d_conv[(size_t)(s0 + r) * CONV_DIM + 2 * KEY_DIM + h * DV + c4];
        float b = bt[r];
        KBs[r * PADK + c4 + 0] = vv.x * b; KBs[r * PADK + c4 + 1] = vv.y * b;
        KBs[r * PADK + c4 + 2] = vv.z * b; KBs[r * PADK + c4 + 3] = vv.w * b;
    }
    __syncthreads();

    // u = (Am + I) @ (v*beta)
    for (int t = tid; t < 8192; t += 256) {
        int i = t >> 7, dv = t & 127;
        float acc = KBs[i * PADK + dv];
        for (int j = 0; j < i; j++) acc += Am[i * 64 + j] * KBs[j * PADK + dv];
        d_u[((size_t)h * S_LEN + s0 + i) * DV + dv] = acc;
    }
}

// ---------------- cross-chunk sequential state scan ----------------
// grid (4, NV): each block owns head h and 32 DV columns; state [128][32] in smem.
__global__ __launch_bounds__(256) void scan_kernel() {
    int grp = blockIdx.x;
    int h = blockIdx.y;
    int h2 = h >> 1;
    int c0 = grp * 32;
    extern __shared__ float sm[];
    float* state = sm;                 // 128*33
    float* T = state + 128 * 33;       // 64*132 (kcd / q*exp(g) / k*exp(gl-g))
    float* vnew = T + 64 * PADK;       // 64*33
    float* sc = vnew + 64 * 33;        // 64*64
    float* gc = sc + 4096;             // 64
    int tid = threadIdx.x;

    for (int t = tid; t < 128 * 33; t += 256) state[t] = 0.f;
    __syncthreads();

    for (int cid = 0; cid < NCHUNK; cid++) {
        int s0 = cid * CHUNK;
        if (tid < 64) gc[tid] = d_g[h * S_LEN + s0 + tid];
        __syncthreads();
        float gl = gc[63];

        // T <- kcd tile
        for (int t = tid; t < 64 * 32; t += 256) {
            int r = t >> 5, c4 = (t & 31) << 2;
            float4 v = *(const float4*)&d_kcd[((size_t)h * S_LEN + s0 + r) * DK + c4];
            T[r * PADK + c4 + 0] = v.x; T[r * PADK + c4 + 1] = v.y;
            T[r * PADK + c4 + 2] = v.z; T[r * PADK + c4 + 3] = v.w;
        }
        __syncthreads();

        // vnew = u - kcd @ state
        for (int t = tid; t < 2048; t += 256) {
            int c = t >> 5, j = t & 31;
            float acc = d_u[((size_t)h * S_LEN + s0 + c) * DV + c0 + j];
            const float* Tr = T + c * PADK;
#pragma unroll 4
            for (int d = 0; d < 128; d++) acc -= Tr[d] * state[d * 33 + j];
            vnew[c * 33 + j] = acc;
        }
        __syncthreads();

        // T <- q*exp(gc); sc <- scores
        for (int t = tid; t < 64 * 32; t += 256) {
            int r = t >> 5, c4 = (t & 31) << 2;
            float4 v = *(const float4*)&d_qn[((size_t)(s0 + r) * NK + h2) * DK + c4];
            float e = expf(gc[r]);
            T[r * PADK + c4 + 0] = v.x * e; T[r * PADK + c4 + 1] = v.y * e;
            T[r * PADK + c4 + 2] = v.z * e; T[r * PADK + c4 + 3] = v.w * e;
        }
        for (int t = tid; t < 4096; t += 256)
            sc[t] = d_scores[(size_t)(h * NCHUNK + cid) * 4096 + t];
        __syncthreads();

        // o = (q*exp(g)) @ state + scores @ vnew
        for (int t = tid; t < 2048; t += 256) {
            int c = t >> 5, j = t & 31;
            float acc = 0.f;
            const float* Tr = T + c * PADK;
#pragma unroll 4
            for (int d = 0; d < 128; d++) acc += Tr[d] * state[d * 33 + j];
            const float* scr = sc + c * 64;
            for (int c2 = 0; c2 <= c; c2++) acc += scr[c2] * vnew[c2 * 33 + j];
            d_o[(size_t)(s0 + c) * VAL_DIM + h * DV + c0 + j] = acc;
        }
        __syncthreads();

        // T <- k*exp(gl-gc)
        for (int t = tid; t < 64 * 32; t += 256) {
            int r = t >> 5, c4 = (t & 31) << 2;
            float4 v = *(const float4*)&d_kn[((size_t)(s0 + r) * NK + h2) * DK + c4];
            float e = expf(gl - gc[r]);
            T[r * PADK + c4 + 0] = v.x * e; T[r * PADK + c4 + 1] = v.y * e;
            T[r * PADK + c4 + 2] = v.z * e; T[r * PADK + c4 + 3] = v.w * e;
        }
        __syncthreads();

        // state = state*exp(gl) + (k*exp(gl-g))^T @ vnew
        float egl = expf(gl);
        for (int t = tid; t < 4096; t += 256) {
            int d = t >> 5, j = t & 31;
            float acc = state[d * 33 + j] * egl;
#pragma unroll 4
            for (int c = 0; c < 64; c++) acc += T[c * PADK + d] * vnew[c * 33 + j];
            state[d * 33 + j] = acc;
        }
        __syncthreads();
    }
}

// ---------------- RMS-norm + silu(z) gate ----------------
__global__ __launch_bounds__(256) void norm_gate(const float* __restrict__ norm_w) {
    int gw = (blockIdx.x * 256 + threadIdx.x) >> 5;  // S*NV rows
    int lane = threadIdx.x & 31;
    int s = gw >> 5;
    int h = gw & 31;
    size_t base = (size_t)s * VAL_DIM + h * DV + lane * 4;
    float4 v = *(const float4*)(d_o + base);
    float ss = v.x * v.x + v.y * v.y + v.z * v.z + v.w * v.w;
#pragma unroll
    for (int o = 16; o; o >>= 1) ss += __shfl_xor_sync(0xffffffffu, ss, o);
    float r = rsqrtf(ss * (1.f / 128.f) + 1e-6f);
    float4 z = *(const float4*)(d_zbuf + base);
    float4 w = *(const float4*)(norm_w + lane * 4);
    float4 o4;
    o4.x = v.x * r * w.x * (z.x / (1.f + expf(-z.x)));
    o4.y = v.y * r * w.y * (z.y / (1.f + expf(-z.y)));
    o4.z = v.z * r * w.z * (z.z / (1.f + expf(-z.z)));
    o4.w = v.w * r * w.w * (z.w / (1.f + expf(-z.w)));
    *(float4*)(d_hbuf + base) = o4;
}

// ---------------- launch ----------------
extern "C" void kernel_launch(void* const* d_in, const int* in_sizes, int n_in,
                              void* d_out, int out_size) {
    const float* x       = (const float*)d_in[0];
    const float* W_qkv   = (const float*)d_in[1];
    const float* W_z     = (const float*)d_in[2];
    const float* W_a     = (const float*)d_in[3];
    const float* W_b     = (const float*)d_in[4];
    const float* conv_w  = (const float*)d_in[5];
    const float* dt_bias = (const float*)d_in[6];
    const float* A_log   = (const float*)d_in[7];
    const float* norm_w  = (const float*)d_in[8];
    const float* W_out   = (const float*)d_in[9];
    float* out = (float*)d_out;

    void *p_mixed, *p_z, *p_h;
    cudaGetSymbolAddress(&p_mixed, d_mixed);
    cudaGetSymbolAddress(&p_z, d_zbuf);
    cudaGetSymbolAddress(&p_h, d_hbuf);

    int chunk_smem = (3 * 64 * PADK + 64 * 64 + 3 * 64) * (int)sizeof(float);
    int scan_smem  = (128 * 33 + 64 * PADK + 64 * 33 + 64 * 64 + 64) * (int)sizeof(float);
    cudaFuncSetAttribute(chunk_kernel, cudaFuncAttributeMaxDynamicSharedMemorySize, chunk_smem);
    cudaFuncSetAttribute(scan_kernel,  cudaFuncAttributeMaxDynamicSharedMemorySize, scan_smem);

    // projections
    sgemm_tn<<<dim3(CONV_DIM / 128, S_LEN / 128), 256>>>(x, W_qkv, (float*)p_mixed, S_LEN, CONV_DIM, HID);
    sgemm_tn<<<dim3(VAL_DIM / 128, S_LEN / 128), 256>>>(x, W_z, (float*)p_z, S_LEN, VAL_DIM, HID);
    proj_ab<<<(S_LEN * NV * 2) / 8, 256>>>(x, W_a, W_b, dt_bias, A_log);
    g_cumsum<<<NV * NCHUNK, CHUNK>>>();

    // conv + silu, qk l2norm
    conv_silu<<<(S_LEN * CONV_DIM) / 256, 256>>>(conv_w);
    qk_norm<<<(S_LEN * NK * 2) / 8, 256>>>();

    // delta rule
    chunk_kernel<<<dim3(NCHUNK, NV), 256, chunk_smem>>>();
    scan_kernel<<<dim3(4, NV), 256, scan_smem>>>();

    // norm + gate + output projection
    norm_gate<<<(S_LEN * NV) / 8, 256>>>(norm_w);
    sgemm_tn<<<dim3(HID / 128, S_LEN / 128), 256>>>((const float*)p_h, W_out, out, S_LEN, HID, VAL_DIM);
}

// round 4
// speedup vs baseline: 1.5782x; 1.5782x over previous
#include <cuda_runtime.h>
#include <cuda_bf16.h>
#include <math.h>
#include <stdint.h>

#define S_LEN 2048
#define HID 2048
#define NK 16
#define NV 32
#define DK 128
#define DV 128
#define KSZ 4
#define CHUNK 64
#define NCHUNK (S_LEN / CHUNK)
#define KEY_DIM (NK * DK)          // 2048
#define VAL_DIM (NV * DV)          // 4096
#define CONV_DIM (2 * KEY_DIM + VAL_DIM)  // 8192

// ---------------- scratch (static device globals; no allocation) ----------------
__device__ float d_mixed[(size_t)S_LEN * CONV_DIM];   // pre-conv projections
__device__ float d_conv[(size_t)S_LEN * CONV_DIM];    // post conv + silu
__device__ float d_zbuf[(size_t)S_LEN * VAL_DIM];
__device__ float d_g[NV * S_LEN];                     // per-chunk cumsum'd gate, [h][s]
__device__ float d_beta[NV * S_LEN];                  // [h][s]
__device__ float d_qn[(size_t)S_LEN * NK * DK];       // l2norm(q) * DK^-0.5
__device__ float d_kn[(size_t)S_LEN * NK * DK];       // l2norm(k)
__device__ float d_u[(size_t)NV * S_LEN * DV];        // [h][s][dv]
__device__ float d_kcd[(size_t)NV * S_LEN * DK];      // [h][s][dk]
__device__ float d_scores[(size_t)NV * NCHUNK * CHUNK * CHUNK];
__device__ float d_o[(size_t)S_LEN * VAL_DIM];        // core output, [s][h*DV+dv]

// bf16 split buffers (hi/lo) for tensor-core GEMMs
__device__ __nv_bfloat16 d_xh[(size_t)S_LEN * HID];
__device__ __nv_bfloat16 d_xl[(size_t)S_LEN * HID];
__device__ __nv_bfloat16 d_wqh[(size_t)CONV_DIM * HID];
__device__ __nv_bfloat16 d_wql[(size_t)CONV_DIM * HID];
__device__ __nv_bfloat16 d_wzh[(size_t)VAL_DIM * HID];
__device__ __nv_bfloat16 d_wzl[(size_t)VAL_DIM * HID];
__device__ __nv_bfloat16 d_woh[(size_t)HID * VAL_DIM];
__device__ __nv_bfloat16 d_wol[(size_t)HID * VAL_DIM];
__device__ __nv_bfloat16 d_hh[(size_t)S_LEN * VAL_DIM];
__device__ __nv_bfloat16 d_hl[(size_t)S_LEN * VAL_DIM];

// ================= helpers =================
__device__ __forceinline__ uint32_t smem_u32_of(const void* p) {
    uint32_t a;
    asm("{ .reg .u64 t; cvta.to.shared.u64 t, %1; cvt.u32.u64 %0, t; }" : "=r"(a) : "l"(p));
    return a;
}

#define LDMATRIX_X4(r0, r1, r2, r3, addr)                                        \
    asm volatile("ldmatrix.sync.aligned.m8n8.x4.shared.b16 {%0,%1,%2,%3}, [%4];" \
                 : "=r"(r0), "=r"(r1), "=r"(r2), "=r"(r3) : "r"(addr))

#define MMA_BF16(c, a, b)                                                        \
    asm volatile("mma.sync.aligned.m16n8k16.row.col.f32.bf16.bf16.f32 "          \
                 "{%0,%1,%2,%3}, {%4,%5,%6,%7}, {%8,%9}, {%0,%1,%2,%3};"         \
                 : "+f"((c)[0]), "+f"((c)[1]), "+f"((c)[2]), "+f"((c)[3])        \
                 : "r"((a)[0]), "r"((a)[1]), "r"((a)[2]), "r"((a)[3]),           \
                   "r"((b)[0]), "r"((b)[1]))

// =============== mma.sync bf16 3-term split GEMM: C[M,N] = A @ B^T ===============
// A: [M,K] hi/lo bf16 row-major; B: [N,K] hi/lo bf16 row-major; C fp32 row-major.
// Block tile 128x128, 8 warps (2x4), warp tile 64x32, BK=32, cp.async double buffer.
// SMEM rows padded to 40 bf16 (80B) -> conflict-free ldmatrix.
#define APAD 40
#define MAT_ELEMS (128 * APAD)            // 5120 per matrix
#define STAGE_ELEMS (4 * MAT_ELEMS)       // Ah, Al, Bh, Bl
#define GEMM_SMEM (2 * STAGE_ELEMS * 2)   // bytes = 81920

__device__ __forceinline__ void stage_load(
    uint32_t stage_base_bytes,
    const __nv_bfloat16* __restrict__ Ah, const __nv_bfloat16* __restrict__ Al,
    const __nv_bfloat16* __restrict__ Bh, const __nv_bfloat16* __restrict__ Bl,
    int bm, int bn, int K, int k0, int tid) {
#pragma unroll
    for (int i = 0; i < 8; i++) {
        int id = tid + i * 256;        // 0..2047
        int mat = id >> 9;             // 0..3
        int rem = id & 511;
        int row = rem >> 2;            // 0..127
        int ch  = rem & 3;             // 16B chunk within 64B row
        const __nv_bfloat16* base = (mat == 0) ? Ah : (mat == 1) ? Al : (mat == 2) ? Bh : Bl;
        int grow = (mat < 2) ? (bm + row) : (bn + row);
        const __nv_bfloat16* g = base + (size_t)grow * K + k0 + ch * 8;
        uint32_t dst = stage_base_bytes + (uint32_t)(mat * MAT_ELEMS + row * APAD + ch * 8) * 2;
        asm volatile("cp.async.cg.shared.global [%0], [%1], 16;" :: "r"(dst), "l"(g) : "memory");
    }
    asm volatile("cp.async.commit_group;" ::: "memory");
}

__global__ __launch_bounds__(256, 1)
void gemm_mma(const __nv_bfloat16* __restrict__ Ah, const __nv_bfloat16* __restrict__ Al,
              const __nv_bfloat16* __restrict__ Bh, const __nv_bfloat16* __restrict__ Bl,
              float* __restrict__ C, int M, int N, int K) {
    extern __shared__ __nv_bfloat16 smB[];
    const int tid = threadIdx.x;
    const int lane = tid & 31;
    const int w = tid >> 5;
    const int wm = w >> 2;             // 0..1
    const int wn = w & 3;              // 0..3
    const int bm = blockIdx.y * 128, bn = blockIdx.x * 128;
    const uint32_t smb = smem_u32_of(smB);

    float acc[4][4][4];
#pragma unroll
    for (int mt = 0; mt < 4; mt++)
#pragma unroll
        for (int nt = 0; nt < 4; nt++)
#pragma unroll
            for (int r = 0; r < 4; r++) acc[mt][nt][r] = 0.f;

    // per-thread ldmatrix element offsets (within a matrix tile)
    const uint32_t aoff = (uint32_t)((wm * 64 + (lane & 15)) * APAD + (lane >> 4) * 8) * 2;
    const uint32_t boff = (uint32_t)((wn * 32 + ((lane >> 4) & 1) * 8 + (lane & 7)) * APAD
                                     + ((lane >> 3) & 1) * 8) * 2;

    const int nkt = K >> 5;
    stage_load(smb, Ah, Al, Bh, Bl, bm, bn, K, 0, tid);
    stage_load(smb + STAGE_ELEMS * 2, Ah, Al, Bh, Bl, bm, bn, K, 32, tid);

    for (int kt = 0; kt < nkt; kt++) {
        asm volatile("cp.async.wait_group 1;" ::: "memory");
        __syncthreads();
        uint32_t sb = smb + (uint32_t)(kt & 1) * (STAGE_ELEMS * 2);
        uint32_t sAh = sb + aoff;
        uint32_t sAl = sAh + MAT_ELEMS * 2;
        uint32_t sBh = sb + 2 * MAT_ELEMS * 2 + boff;
        uint32_t sBl = sBh + MAT_ELEMS * 2;

#pragma unroll
        for (int ks = 0; ks < 2; ks++) {
            uint32_t ah[4][4], al[4][4], bh[2][4], bl[2][4];
            uint32_t kadd = (uint32_t)(ks * 16) * 2;
#pragma unroll
            for (int mt = 0; mt < 4; mt++) {
                uint32_t ad = sAh + (uint32_t)(mt * 16 * APAD) * 2 + kadd;
                LDMATRIX_X4(ah[mt][0], ah[mt][1], ah[mt][2], ah[mt][3], ad);
                uint32_t ad2 = sAl + (uint32_t)(mt * 16 * APAD) * 2 + kadd;
                LDMATRIX_X4(al[mt][0], al[mt][1], al[mt][2], al[mt][3], ad2);
            }
#pragma unroll
            for (int bt = 0; bt < 2; bt++) {
                uint32_t bd = sBh + (uint32_t)(bt * 16 * APAD) * 2 + kadd;
                LDMATRIX_X4(bh[bt][0], bh[bt][1], bh[bt][2], bh[bt][3], bd);
                uint32_t bd2 = sBl + (uint32_t)(bt * 16 * APAD) * 2 + kadd;
                LDMATRIX_X4(bl[bt][0], bl[bt][1], bl[bt][2], bl[bt][3], bd2);
            }
#pragma unroll
            for (int mt = 0; mt < 4; mt++)
#pragma unroll
                for (int nt = 0; nt < 4; nt++) {
                    uint32_t bfh[2] = {bh[nt >> 1][(nt & 1) * 2], bh[nt >> 1][(nt & 1) * 2 + 1]};
                    uint32_t bfl[2] = {bl[nt >> 1][(nt & 1) * 2], bl[nt >> 1][(nt & 1) * 2 + 1]};
                    MMA_BF16(acc[mt][nt], ah[mt], bfh);
                    MMA_BF16(acc[mt][nt], ah[mt], bfl);
                    MMA_BF16(acc[mt][nt], al[mt], bfh);
                }
        }
        __syncthreads();
        if (kt + 2 < nkt)
            stage_load(smb + (uint32_t)(kt & 1) * (STAGE_ELEMS * 2),
                       Ah, Al, Bh, Bl, bm, bn, K, (kt + 2) * 32, tid);
    }

    // epilogue: c-frag rows lane/4 (+8), cols (lane%4)*2 (+1)
    int r0 = bm + wm * 64 + (lane >> 2);
    int cc = bn + wn * 32 + (lane & 3) * 2;
#pragma unroll
    for (int mt = 0; mt < 4; mt++) {
#pragma unroll
        for (int nt = 0; nt < 4; nt++) {
            float* p0 = C + (size_t)(r0 + mt * 16) * N + cc + nt * 8;
            float* p1 = p0 + 8 * N;
            *(float2*)p0 = make_float2(acc[mt][nt][0], acc[mt][nt][1]);
            *(float2*)p1 = make_float2(acc[mt][nt][2], acc[mt][nt][3]);
        }
    }
}

// ---------------- fp32 -> bf16 hi/lo split ----------------
__global__ __launch_bounds__(256) void split_fp32(
    const float* __restrict__ src, __nv_bfloat16* __restrict__ hi,
    __nv_bfloat16* __restrict__ lo, int n4) {
    int i = blockIdx.x * 256 + threadIdx.x;
    if (i >= n4) return;
    float4 v = ((const float4*)src)[i];
    __nv_bfloat16 h0 = __float2bfloat16(v.x), h1 = __float2bfloat16(v.y);
    __nv_bfloat16 h2 = __float2bfloat16(v.z), h3 = __float2bfloat16(v.w);
    __nv_bfloat16 l0 = __float2bfloat16(v.x - __bfloat162float(h0));
    __nv_bfloat16 l1 = __float2bfloat16(v.y - __bfloat162float(h1));
    __nv_bfloat16 l2 = __float2bfloat16(v.z - __bfloat162float(h2));
    __nv_bfloat16 l3 = __float2bfloat16(v.w - __bfloat162float(h3));
    ((__nv_bfloat162*)hi)[2 * i]     = __nv_bfloat162(h0, h1);
    ((__nv_bfloat162*)hi)[2 * i + 1] = __nv_bfloat162(h2, h3);
    ((__nv_bfloat162*)lo)[2 * i]     = __nv_bfloat162(l0, l1);
    ((__nv_bfloat162*)lo)[2 * i + 1] = __nv_bfloat162(l2, l3);
}

// ---------------- a/b projections -> raw g and beta ----------------
__global__ __launch_bounds__(256) void proj_ab(
    const float* __restrict__ x, const float* __restrict__ Wa,
    const float* __restrict__ Wb, const float* __restrict__ dt_bias,
    const float* __restrict__ A_log) {
    int gw = (blockIdx.x * 256 + threadIdx.x) >> 5;
    int lane = threadIdx.x & 31;
    int which = gw & 1;
    int h = (gw >> 1) & (NV - 1);
    int s = gw >> 6;
    const float* xr = x + (size_t)s * HID;
    const float* wr = (which ? Wb : Wa) + (size_t)h * HID;
    float sum = 0.f;
    for (int i = lane * 4; i < HID; i += 128) {
        float4 a = *(const float4*)(xr + i);
        float4 b = *(const float4*)(wr + i);
        sum += a.x * b.x + a.y * b.y + a.z * b.z + a.w * b.w;
    }
#pragma unroll
    for (int o = 16; o; o >>= 1) sum += __shfl_xor_sync(0xffffffffu, sum, o);
    if (lane == 0) {
        if (which) {
            d_beta[h * S_LEN + s] = 1.f / (1.f + expf(-sum));
        } else {
            float xv = sum + dt_bias[h];
            float sp = fmaxf(xv, 0.f) + log1pf(expf(-fabsf(xv)));  // stable softplus
            d_g[h * S_LEN + s] = -expf(A_log[h]) * sp;
        }
    }
}

// ---------------- per-chunk inclusive cumsum of g ----------------
__global__ void g_cumsum() {
    int h = blockIdx.x >> 5;       // NCHUNK = 32
    int c = blockIdx.x & 31;
    __shared__ float buf[CHUNK];
    int i = threadIdx.x;
    buf[i] = d_g[h * S_LEN + c * CHUNK + i];
    __syncthreads();
#pragma unroll
    for (int off = 1; off < CHUNK; off <<= 1) {
        float v = (i >= off) ? buf[i - off] : 0.f;
        __syncthreads();
        buf[i] += v;
        __syncthreads();
    }
    d_g[h * S_LEN + c * CHUNK + i] = buf[i];
}

// ---------------- causal depthwise conv (K=4) + SiLU ----------------
__global__ __launch_bounds__(256) void conv_silu(const float* __restrict__ w) {
    int idx = blockIdx.x * 256 + threadIdx.x;  // S*CONV_DIM
    int c = idx % CONV_DIM;
    int s = idx / CONV_DIM;
    float acc = 0.f;
#pragma unroll
    for (int t = 0; t < KSZ; t++) {
        int sp = s - (KSZ - 1) + t;
        if (sp >= 0) acc += d_mixed[(size_t)sp * CONV_DIM + c] * w[c * KSZ + t];
    }
    d_conv[idx] = acc / (1.f + expf(-acc));  // silu
}

// ---------------- l2norm of q,k (16 source heads); q also * DK^-0.5 ----------------
__global__ __launch_bounds__(256) void qk_norm() {
    int gw = (blockIdx.x * 256 + threadIdx.x) >> 5;  // S*NK*2 warps
    int lane = threadIdx.x & 31;
    int which = gw & 1;                 // 0=q, 1=k
    int hk = (gw >> 1) & (NK - 1);
    int s = gw >> 5;
    const float* src = d_conv + (size_t)s * CONV_DIM + which * KEY_DIM + hk * DK + lane * 4;
    float4 v = *(const float4*)src;
    float ss = v.x * v.x + v.y * v.y + v.z * v.z + v.w * v.w;
#pragma unroll
    for (int o = 16; o; o >>= 1) ss += __shfl_xor_sync(0xffffffffu, ss, o);
    float r = rsqrtf(ss + 1e-6f);
    if (!which) r *= 0.08838834764831845f;  // DK^-0.5
    float* dst = (which ? d_kn : d_qn) + ((size_t)s * NK + hk) * DK + lane * 4;
    v.x *= r; v.y *= r; v.z *= r; v.w *= r;
    *(float4*)dst = v;
}

// ---------------- chunk-local: scores, UT transform, u, kcd ----------------
#define PADK 132
__global__ __launch_bounds__(256) void chunk_kernel() {
    int cid = blockIdx.x;
    int h = blockIdx.y;
    int h2 = h >> 1;                 // q/k source head (repeat ratio 2)
    int s0 = cid * CHUNK;
    extern __shared__ float smf[];
    float* Ks = smf;                   // 64*132 (normalized k)
    float* KBs = Ks + 64 * PADK;       // 64*132 (k*beta, later v*beta)
    float* Qs = KBs + 64 * PADK;       // 64*132
    float* Am = Qs + 64 * PADK;        // 64*64
    float* gc = Am + 64 * 64;          // 64
    float* bt = gc + 64;               // 64
    float* rowbuf = bt + 64;           // 64
    int tid = threadIdx.x;

    if (tid < 64) {
        gc[tid] = d_g[h * S_LEN + s0 + tid];
        bt[tid] = d_beta[h * S_LEN + s0 + tid];
    }
    __syncthreads();

    for (int t = tid; t < 64 * 32; t += 256) {
        int r = t >> 5, c4 = (t & 31) << 2;
        float4 kv = *(const float4*)&d_kn[((size_t)(s0 + r) * NK + h2) * DK + c4];
        float4 qv = *(const float4*)&d_qn[((size_t)(s0 + r) * NK + h2) * DK + c4];
        float b = bt[r];
        Ks[r * PADK + c4 + 0] = kv.x; Ks[r * PADK + c4 + 1] = kv.y;
        Ks[r * PADK + c4 + 2] = kv.z; Ks[r * PADK + c4 + 3] = kv.w;
        Qs[r * PADK + c4 + 0] = qv.x; Qs[r * PADK + c4 + 1] = qv.y;
        Qs[r * PADK + c4 + 2] = qv.z; Qs[r * PADK + c4 + 3] = qv.w;
        KBs[r * PADK + c4 + 0] = kv.x * b; KBs[r * PADK + c4 + 1] = kv.y * b;
        KBs[r * PADK + c4 + 2] = kv.z * b; KBs[r * PADK + c4 + 3] = kv.w * b;
    }
    __syncthreads();

    for (int t = tid; t < 4096; t += 256) {
        int i = t >> 6, j = t & 63;
        float sc = 0.f, am = 0.f;
        if (i >= j) {
            float dq = 0.f, dk = 0.f;
            const float* kr = Ks + j * PADK;
            const float* qr = Qs + i * PADK;
            const float* kbr = KBs + i * PADK;
#pragma unroll 4
            for (int d = 0; d < 128; d++) {
                float kj = kr[d];
                dq += qr[d] * kj;
                dk += kbr[d] * kj;
            }
            float e = expf(gc[i] - gc[j]);
            sc = dq * e;
            if (i > j) am = -dk * e;
        }
        d_scores[(size_t)(h * NCHUNK + cid) * 4096 + t] = sc;
        Am[t] = am;
    }
    __syncthreads();

    for (int i = 1; i < 64; i++) {
        if (tid < i) {
            int j = tid;
            float sum = Am[i * 64 + j];
            for (int k = j + 1; k < i; k++) sum += Am[i * 64 + k] * Am[k * 64 + j];
            rowbuf[j] = sum;
        }
        __syncthreads();
        if (tid < i) Am[i * 64 + tid] = rowbuf[tid];
        __syncthreads();
    }

    if (tid < 64) rowbuf[tid] = expf(gc[tid]);
    __syncthreads();
    for (int t = tid; t < 64 * 128; t += 256) {
        int r = t >> 7, d = t & 127;
        KBs[r * PADK + d] *= rowbuf[r];
    }
    __syncthreads();

    for (int t = tid; t < 8192; t += 256) {
        int i = t >> 7, dk = t & 127;
        float acc = KBs[i * PADK + dk];
        for (int j = 0; j < i; j++) acc += Am[i * 64 + j] * KBs[j * PADK + dk];
        d_kcd[((size_t)h * S_LEN + s0 + i) * DK + dk] = acc;
    }
    __syncthreads();

    for (int t = tid; t < 64 * 32; t += 256) {
        int r = t >> 5, c4 = (t & 31) << 2;
        float4 vv = *(const float4*)&d_conv[(size_t)(s0 + r) * CONV_DIM + 2 * KEY_DIM + h * DV + c4];
        float b = bt[r];
        KBs[r * PADK + c4 + 0] = vv.x * b; KBs[r * PADK + c4 + 1] = vv.y * b;
        KBs[r * PADK + c4 + 2] = vv.z * b; KBs[r * PADK + c4 + 3] = vv.w * b;
    }
    __syncthreads();

    for (int t = tid; t < 8192; t += 256) {
        int i = t >> 7, dv = t & 127;
        float acc = KBs[i * PADK + dv];
        for (int j = 0; j < i; j++) acc += Am[i * 64 + j] * KBs[j * PADK + dv];
        d_u[((size_t)h * S_LEN + s0 + i) * DV + dv] = acc;
    }
}

// ---------------- cross-chunk sequential state scan ----------------
__global__ __launch_bounds__(256) void scan_kernel() {
    int grp = blockIdx.x;
    int h = blockIdx.y;
    int h2 = h >> 1;
    int c0 = grp * 32;
    extern __shared__ float smf[];
    float* state = smf;                // 128*33
    float* T = state + 128 * 33;       // 64*132
    float* vnew = T + 64 * PADK;       // 64*33
    float* sc = vnew + 64 * 33;        // 64*64
    float* gc = sc + 4096;             // 64
    int tid = threadIdx.x;

    for (int t = tid; t < 128 * 33; t += 256) state[t] = 0.f;
    __syncthreads();

    for (int cid = 0; cid < NCHUNK; cid++) {
        int s0 = cid * CHUNK;
        if (tid < 64) gc[tid] = d_g[h * S_LEN + s0 + tid];
        __syncthreads();
        float gl = gc[63];

        for (int t = tid; t < 64 * 32; t += 256) {
            int r = t >> 5, c4 = (t & 31) << 2;
            float4 v = *(const float4*)&d_kcd[((size_t)h * S_LEN + s0 + r) * DK + c4];
            T[r * PADK + c4 + 0] = v.x; T[r * PADK + c4 + 1] = v.y;
            T[r * PADK + c4 + 2] = v.z; T[r * PADK + c4 + 3] = v.w;
        }
        __syncthreads();

        for (int t = tid; t < 2048; t += 256) {
            int c = t >> 5, j = t & 31;
            float acc = d_u[((size_t)h * S_LEN + s0 + c) * DV + c0 + j];
            const float* Tr = T + c * PADK;
#pragma unroll 4
            for (int d = 0; d < 128; d++) acc -= Tr[d] * state[d * 33 + j];
            vnew[c * 33 + j] = acc;
        }
        __syncthreads();

        for (int t = tid; t < 64 * 32; t += 256) {
            int r = t >> 5, c4 = (t & 31) << 2;
            float4 v = *(const float4*)&d_qn[((size_t)(s0 + r) * NK + h2) * DK + c4];
            float e = expf(gc[r]);
            T[r * PADK + c4 + 0] = v.x * e; T[r * PADK + c4 + 1] = v.y * e;
            T[r * PADK + c4 + 2] = v.z * e; T[r * PADK + c4 + 3] = v.w * e;
        }
        for (int t = tid; t < 4096; t += 256)
            sc[t] = d_scores[(size_t)(h * NCHUNK + cid) * 4096 + t];
        __syncthreads();

        for (int t = tid; t < 2048; t += 256) {
            int c = t >> 5, j = t & 31;
            float acc = 0.f;
            const float* Tr = T + c * PADK;
#pragma unroll 4
            for (int d = 0; d < 128; d++) acc += Tr[d] * state[d * 33 + j];
            const float* scr = sc + c * 64;
            for (int c2 = 0; c2 <= c; c2++) acc += scr[c2] * vnew[c2 * 33 + j];
            d_o[(size_t)(s0 + c) * VAL_DIM + h * DV + c0 + j] = acc;
        }
        __syncthreads();

        for (int t = tid; t < 64 * 32; t += 256) {
            int r = t >> 5, c4 = (t & 31) << 2;
            float4 v = *(const float4*)&d_kn[((size_t)(s0 + r) * NK + h2) * DK + c4];
            float e = expf(gl - gc[r]);
            T[r * PADK + c4 + 0] = v.x * e; T[r * PADK + c4 + 1] = v.y * e;
            T[r * PADK + c4 + 2] = v.z * e; T[r * PADK + c4 + 3] = v.w * e;
        }
        __syncthreads();

        float egl = expf(gl);
        for (int t = tid; t < 4096; t += 256) {
            int d = t >> 5, j = t & 31;
            float acc = state[d * 33 + j] * egl;
#pragma unroll 4
            for (int c = 0; c < 64; c++) acc += T[c * PADK + d] * vnew[c * 33 + j];
            state[d * 33 + j] = acc;
        }
        __syncthreads();
    }
}

// ---------------- RMS-norm + silu(z) gate -> bf16 hi/lo split ----------------
__global__ __launch_bounds__(256) void norm_gate(const float* __restrict__ norm_w) {
    int gw = (blockIdx.x * 256 + threadIdx.x) >> 5;  // S*NV rows
    int lane = threadIdx.x & 31;
    int s = gw >> 5;
    int h = gw & 31;
    size_t base = (size_t)s * VAL_DIM + h * DV + lane * 4;
    float4 v = *(const float4*)(d_o + base);
    float ss = v.x * v.x + v.y * v.y + v.z * v.z + v.w * v.w;
#pragma unroll
    for (int o = 16; o; o >>= 1) ss += __shfl_xor_sync(0xffffffffu, ss, o);
    float r = rsqrtf(ss * (1.f / 128.f) + 1e-6f);
    float4 z = *(const float4*)(d_zbuf + base);
    float4 w = *(const float4*)(norm_w + lane * 4);
    float o0 = v.x * r * w.x * (z.x / (1.f + expf(-z.x)));
    float o1 = v.y * r * w.y * (z.y / (1.f + expf(-z.y)));
    float o2 = v.z * r * w.z * (z.z / (1.f + expf(-z.z)));
    float o3 = v.w * r * w.w * (z.w / (1.f + expf(-z.w)));
    __nv_bfloat16 h0 = __float2bfloat16(o0), h1 = __float2bfloat16(o1);
    __nv_bfloat16 h2 = __float2bfloat16(o2), h3 = __float2bfloat16(o3);
    __nv_bfloat16 l0 = __float2bfloat16(o0 - __bfloat162float(h0));
    __nv_bfloat16 l1 = __float2bfloat16(o1 - __bfloat162float(h1));
    __nv_bfloat16 l2 = __float2bfloat16(o2 - __bfloat162float(h2));
    __nv_bfloat16 l3 = __float2bfloat16(o3 - __bfloat162float(h3));
    ((__nv_bfloat162*)d_hh)[base / 2]     = __nv_bfloat162(h0, h1);
    ((__nv_bfloat162*)d_hh)[base / 2 + 1] = __nv_bfloat162(h2, h3);
    ((__nv_bfloat162*)d_hl)[base / 2]     = __nv_bfloat162(l0, l1);
    ((__nv_bfloat162*)d_hl)[base / 2 + 1] = __nv_bfloat162(l2, l3);
}

// ---------------- launch ----------------
extern "C" void kernel_launch(void* const* d_in, const int* in_sizes, int n_in,
                              void* d_out, int out_size) {
    const float* x       = (const float*)d_in[0];
    const float* W_qkv   = (const float*)d_in[1];
    const float* W_z     = (const float*)d_in[2];
    const float* W_a     = (const float*)d_in[3];
    const float* W_b     = (const float*)d_in[4];
    const float* conv_w  = (const float*)d_in[5];
    const float* dt_bias = (const float*)d_in[6];
    const float* A_log   = (const float*)d_in[7];
    const float* norm_w  = (const float*)d_in[8];
    const float* W_out   = (const float*)d_in[9];
    float* out = (float*)d_out;

    void *p_mixed, *p_z, *p_xh, *p_xl, *p_wqh, *p_wql, *p_wzh, *p_wzl;
    void *p_woh, *p_wol, *p_hh, *p_hl;
    cudaGetSymbolAddress(&p_mixed, d_mixed);
    cudaGetSymbolAddress(&p_z, d_zbuf);
    cudaGetSymbolAddress(&p_xh, d_xh);   cudaGetSymbolAddress(&p_xl, d_xl);
    cudaGetSymbolAddress(&p_wqh, d_wqh); cudaGetSymbolAddress(&p_wql, d_wql);
    cudaGetSymbolAddress(&p_wzh, d_wzh); cudaGetSymbolAddress(&p_wzl, d_wzl);
    cudaGetSymbolAddress(&p_woh, d_woh); cudaGetSymbolAddress(&p_wol, d_wol);
    cudaGetSymbolAddress(&p_hh, d_hh);   cudaGetSymbolAddress(&p_hl, d_hl);

    int chunk_smem = (3 * 64 * PADK + 64 * 64 + 3 * 64) * (int)sizeof(float);
    int scan_smem  = (128 * 33 + 64 * PADK + 64 * 33 + 64 * 64 + 64) * (int)sizeof(float);
    cudaFuncSetAttribute(chunk_kernel, cudaFuncAttributeMaxDynamicSharedMemorySize, chunk_smem);
    cudaFuncSetAttribute(scan_kernel,  cudaFuncAttributeMaxDynamicSharedMemorySize, scan_smem);
    cudaFuncSetAttribute(gemm_mma,     cudaFuncAttributeMaxDynamicSharedMemorySize, GEMM_SMEM);

    // bf16 splits of GEMM operands
    split_fp32<<<(S_LEN * HID / 4 + 255) / 256, 256>>>(x, (__nv_bfloat16*)p_xh, (__nv_bfloat16*)p_xl, S_LEN * HID / 4);
    split_fp32<<<(CONV_DIM * HID / 4 + 255) / 256, 256>>>(W_qkv, (__nv_bfloat16*)p_wqh, (__nv_bfloat16*)p_wql, CONV_DIM * HID / 4);
    split_fp32<<<(VAL_DIM * HID / 4 + 255) / 256, 256>>>(W_z, (__nv_bfloat16*)p_wzh, (__nv_bfloat16*)p_wzl, VAL_DIM * HID / 4);
    split_fp32<<<(HID * VAL_DIM / 4 + 255) / 256, 256>>>(W_out, (__nv_bfloat16*)p_woh, (__nv_bfloat16*)p_wol, HID * VAL_DIM / 4);

    // projections via tensor-core split GEMM (mma.sync)
    gemm_mma<<<dim3(CONV_DIM / 128, S_LEN / 128), 256, GEMM_SMEM>>>(
        (const __nv_bfloat16*)p_xh, (const __nv_bfloat16*)p_xl,
        (const __nv_bfloat16*)p_wqh, (const __nv_bfloat16*)p_wql,
        (float*)p_mixed, S_LEN, CONV_DIM, HID);
    gemm_mma<<<dim3(VAL_DIM / 128, S_LEN / 128), 256, GEMM_SMEM>>>(
        (const __nv_bfloat16*)p_xh, (const __nv_bfloat16*)p_xl,
        (const __nv_bfloat16*)p_wzh, (const __nv_bfloat16*)p_wzl,
        (float*)p_z, S_LEN, VAL_DIM, HID);
    proj_ab<<<(S_LEN * NV * 2) / 8, 256>>>(x, W_a, W_b, dt_bias, A_log);
    g_cumsum<<<NV * NCHUNK, CHUNK>>>();

    conv_silu<<<(S_LEN * CONV_DIM) / 256, 256>>>(conv_w);
    qk_norm<<<(S_LEN * NK * 2) / 8, 256>>>();

    chunk_kernel<<<dim3(NCHUNK, NV), 256, chunk_smem>>>();
    scan_kernel<<<dim3(4, NV), 256, scan_smem>>>();

    norm_gate<<<(S_LEN * NV) / 8, 256>>>(norm_w);
    gemm_mma<<<dim3(HID / 128, S_LEN / 128), 256, GEMM_SMEM>>>(
        (const __nv_bfloat16*)p_hh, (const __nv_bfloat16*)p_hl,
        (const __nv_bfloat16*)p_woh, (const __nv_bfloat16*)p_wol,
        out, S_LEN, HID, VAL_DIM);
}